// round 11
// baseline (speedup 1.0000x reference)
#include <cuda_runtime.h>
#include <cuda_fp16.h>
#include <cuda_pipeline.h>

#define T    512
#define K    4
#define G    20000
#define EPG  3
#define B    512

#define BT     16                  // batches per tile (= half-warp)
#define NBT    (B / BT)            // 32
#define BLKG   512                 // 16 warps, 2 blocks/SM
#define GPB    160                 // g per chunk
#define CPS    14                  // chunks per split
#define NSPLIT 9                   // grid 9*32 = 288 = 1 wave at 2/SM
#define NCHUNK (CPS * NSPLIT)      // 126
#define GPAD   (NCHUNK * GPB)      // 20160
#define BLKP   512                 // prep threads
#define OROW   17                  // s_out row stride (odd -> conflict-free reads)

// h2 fp16, layout [bt][t][b_in] as uint2 (k0k1, k2k3): 2 MB, L2-resident.
__device__ uint2  g_h2u[NBT * T * BT];
// per-g 16B record: {e0*16, e1*16, e2*16 (int bits), b3}
__device__ float4 g_q0[GPAD];

// SMEM (bytes): h2 64K | rec 2x10K (64B/g) | out 2x(160*17*4) = ~105K/block
#define S_H2   0
#define S_REC  65536
#define S_OUT  (65536 + 20480)
#define SMEM_TOTAL (65536 + 20480 + 2 * GPB * OROW * 4)   // 107776

__device__ __forceinline__ float leaky(float x) {
    return x > 0.0f ? x : 0.01f * x;
}

// Packed f32x2 FMA (Blackwell FFMA2) — bit-identical to two scalar fp32 FMAs.
__device__ __forceinline__ float2 ffma2(float2 a, float2 b, float2 c) {
    float2 d;
    asm("{\n\t"
        ".reg .b64 ra, rb, rc, rd;\n\t"
        "mov.b64 ra, {%2, %3};\n\t"
        "mov.b64 rb, {%4, %5};\n\t"
        "mov.b64 rc, {%6, %7};\n\t"
        "fma.rn.f32x2 rd, ra, rb, rc;\n\t"
        "mov.b64 {%0, %1}, rd;\n\t"
        "}"
        : "=f"(d.x), "=f"(d.y)
        : "f"(a.x), "f"(a.y), "f"(b.x), "f"(b.y), "f"(c.x), "f"(c.y));
    return d;
}

// ---------------------------------------------------------------------------
// Prep: blocks [0,512) compute h2; blocks [512, 512+40) pack q0 records.
// ---------------------------------------------------------------------------
#define H2_BLOCKS   512
#define PACK_BLOCKS ((GPAD + BLKP - 1) / BLKP)   // 40

__global__ void prep_kernel(const float*  __restrict__ features,
                            const float4* __restrict__ w1,
                            const float4* __restrict__ b1,
                            const float4* __restrict__ w2,
                            const float4* __restrict__ b2,
                            const int*    __restrict__ edge,
                            const float*  __restrict__ b3) {
    const int tid = threadIdx.x;
    if (blockIdx.x < H2_BLOCKS) {
        const int b_in = tid & 15;                 // batch within tile
        const int ty   = tid >> 4;                 // 0..31
        const int bt   = blockIdx.x & (NBT - 1);   // 0..31
        const int t    = (blockIdx.x >> 5) * 32 + ty;
        const int b    = bt * BT + b_in;

        const float  f   = features[b * T + t];
        const float4 w1v = w1[t];
        const float4 b1v = b1[t];
        const float4 b2v = b2[t];

        const float h0 = leaky(fmaf(f, w1v.x, b1v.x));
        const float h1 = leaky(fmaf(f, w1v.y, b1v.y));
        const float h2 = leaky(fmaf(f, w1v.z, b1v.z));
        const float h3 = leaky(fmaf(f, w1v.w, b1v.w));

        const float4 w20 = w2[t * 4 + 0];
        const float4 w21 = w2[t * 4 + 1];
        const float4 w22 = w2[t * 4 + 2];
        const float4 w23 = w2[t * 4 + 3];

        float4 o;
        o.x = leaky(fmaf(h3, w23.x, fmaf(h2, w22.x, fmaf(h1, w21.x, fmaf(h0, w20.x, b2v.x)))));
        o.y = leaky(fmaf(h3, w23.y, fmaf(h2, w22.y, fmaf(h1, w21.y, fmaf(h0, w20.y, b2v.y)))));
        o.z = leaky(fmaf(h3, w23.z, fmaf(h2, w22.z, fmaf(h1, w21.z, fmaf(h0, w20.z, b2v.z)))));
        o.w = leaky(fmaf(h3, w23.w, fmaf(h2, w22.w, fmaf(h1, w21.w, fmaf(h0, w20.w, b2v.w)))));

        const __half2 p0 = __floats2half2_rn(o.x, o.y);
        const __half2 p1 = __floats2half2_rn(o.z, o.w);
        uint2 p;
        p.x = *reinterpret_cast<const unsigned int*>(&p0);
        p.y = *reinterpret_cast<const unsigned int*>(&p1);
        g_h2u[((size_t)bt * T + t) * BT + b_in] = p;
    } else {
        const int g = (blockIdx.x - H2_BLOCKS) * BLKP + tid;
        if (g >= GPAD) return;
        float4 q = make_float4(0.f, 0.f, 0.f, 0.f);
        if (g < G) {
            q = make_float4(__int_as_float(edge[3 * g + 0] * BT),
                            __int_as_float(edge[3 * g + 1] * BT),
                            __int_as_float(edge[3 * g + 2] * BT),
                            b3[g]);
        }
        g_q0[g] = q;
    }
}

// Stage one chunk's w3 into interleaved record slots rec[g*4 + 1..3].
__device__ __forceinline__ void stage_w3(float4* rec, const float* w3,
                                         int c, int tid) {
    const int nvg = min(GPB, max(0, G - c * GPB));
    const float4* wsrc = reinterpret_cast<const float4*>(w3 + (size_t)c * GPB * 12);
    if (tid < nvg * 3) {
        const int g = tid / 3, part = tid - g * 3;
        __pipeline_memcpy_async(&rec[g * 4 + 1 + part], &wsrc[tid], 16);
    }
}
// Stage one chunk's q0 into rec[g*4 + 0].
__device__ __forceinline__ void stage_q0(float4* rec, int c, int tid) {
    const int nvg = min(GPB, max(0, G - c * GPB));
    if (tid < nvg)
        __pipeline_memcpy_async(&rec[tid * 4], &g_q0[(size_t)c * GPB + tid], 16);
}

// ---------------------------------------------------------------------------
// Gather: 64KB persistent h2 tile, 2 blocks/SM (64 warps), half-warp = one g's
// 16 batches, double-buffered {rec, s_out}, one barrier per chunk, PDL.
// ---------------------------------------------------------------------------
__global__ void __launch_bounds__(BLKG, 2)
gather_kernel(const float* __restrict__ w3, float* __restrict__ out) {
    extern __shared__ char sm[];
    uint2*  s_h2  = reinterpret_cast<uint2*>(sm + S_H2);     // [T*BT]
    float4* s_rec = reinterpret_cast<float4*>(sm + S_REC);   // [2][GPB*4]
    float*  s_out = reinterpret_cast<float*>(sm + S_OUT);    // [2][GPB*OROW]

    const int tid  = threadIdx.x;
    const int bt   = blockIdx.y;
    const int w    = tid >> 5;      // warp 0..15 (= batch row in writeout)
    const int lane = tid & 31;
    const int half = lane >> 4;     // which g of the pair
    const int hb   = lane & 15;     // batch within half (= b_in)

    int c = blockIdx.x;   // first chunk for this split

    // PDL: w3 is a kernel input (independent of prep) — stage while prep runs.
    stage_w3(s_rec, w3, c, tid);
    __pipeline_commit();

    cudaGridDependencySynchronize();   // prep grid done (h2 + q0 ready)

    // Stage persistent h2 tile (4096 x 16B) + first chunk's q0.
    {
        const uint4* src = reinterpret_cast<const uint4*>(g_h2u + (size_t)bt * T * BT);
        uint4*       dst = reinterpret_cast<uint4*>(s_h2);
        #pragma unroll
        for (int i = tid; i < T * BT / 2; i += BLKG)
            __pipeline_memcpy_async(&dst[i], &src[i], 16);
    }
    stage_q0(s_rec, c, tid);
    __pipeline_commit();
    __pipeline_wait_prior(0);
    __syncthreads();

    #pragma unroll 1
    for (int iter = 0; iter < CPS; iter++) {
        const int  buf      = iter & 1;
        const bool has_next = (iter + 1 < CPS);

        // Prefetch next chunk into the other buffer (overlaps compute below).
        if (has_next) {
            const int cn = c + NSPLIT;
            float4* rdst = s_rec + (buf ^ 1) * (GPB * 4);
            stage_w3(rdst, w3, cn, tid);
            stage_q0(rdst, cn, tid);
            __pipeline_commit();
        }

        // Compute: warp w owns 10 g as 5 half-warp pairs; one pass (16 b).
        {
            const float4* rec = s_rec + buf * (GPB * 4);
            float*        ob  = s_out + buf * (GPB * OROW);
            const int gl0 = w * 10;

            #pragma unroll
            for (int pp = 0; pp < 5; pp++) {
                const int gsel = gl0 + 2 * pp + half;

                // One LDS.128 wavefront serves both halves (banks disjoint).
                const float4 q0 = rec[gsel * 4 + 0];
                const float4 q1 = rec[gsel * 4 + 1];
                const float4 q2 = rec[gsel * 4 + 2];
                const float4 q3 = rec[gsel * 4 + 3];

                const uint2 p0 = s_h2[__float_as_int(q0.x) + hb];
                const uint2 p1 = s_h2[__float_as_int(q0.y) + hb];
                const uint2 p2 = s_h2[__float_as_int(q0.z) + hb];

                float2 acc0 = make_float2(q0.w, 0.f);
                float2 acc1 = make_float2(0.f, 0.f);
                acc0 = ffma2(__half22float2(*reinterpret_cast<const __half2*>(&p0.x)),
                             make_float2(q1.x, q1.y), acc0);
                acc1 = ffma2(__half22float2(*reinterpret_cast<const __half2*>(&p0.y)),
                             make_float2(q1.z, q1.w), acc1);
                acc0 = ffma2(__half22float2(*reinterpret_cast<const __half2*>(&p1.x)),
                             make_float2(q2.x, q2.y), acc0);
                acc1 = ffma2(__half22float2(*reinterpret_cast<const __half2*>(&p1.y)),
                             make_float2(q2.z, q2.w), acc1);
                acc0 = ffma2(__half22float2(*reinterpret_cast<const __half2*>(&p2.x)),
                             make_float2(q3.x, q3.y), acc0);
                acc1 = ffma2(__half22float2(*reinterpret_cast<const __half2*>(&p2.y)),
                             make_float2(q3.z, q3.w), acc1);
                const float r = (acc0.x + acc1.x) + (acc0.y + acc1.y);

                // row stride 17: halves' bank sets nearly disjoint; reads perfect.
                ob[gsel * OROW + hb] = r;
            }
        }

        // ONE barrier: publishes s_out[buf]; next compute uses s_out[buf^1].
        __syncthreads();

        // Coalesced write-out: warp = batch row w, lane = consecutive g.
        // Read banks (17*gl + w) & 31 — permutation over gl: conflict-free.
        {
            const float* ob = s_out + buf * (GPB * OROW);
            const int gbase = c * GPB;
            float* orow = out + (size_t)(bt * BT + w) * G + gbase;
            #pragma unroll
            for (int it2 = 0; it2 < GPB / 32; it2++) {
                const int gl = it2 * 32 + lane;
                if (gbase + gl < G)
                    orow[gl] = ob[gl * OROW + w];
            }
        }

        if (has_next) __pipeline_wait_prior(0);   // next rec resident
        c += NSPLIT;
    }
}

extern "C" void kernel_launch(void* const* d_in, const int* in_sizes, int n_in,
                              void* d_out, int out_size) {
    const float* features = (const float*)d_in[0];   // [B, T]
    const float* w1       = (const float*)d_in[1];   // [T, K]
    const float* b1       = (const float*)d_in[2];   // [T, K]
    const float* w2       = (const float*)d_in[3];   // [T, K, K]
    const float* b2       = (const float*)d_in[4];   // [T, K]
    const float* w3       = (const float*)d_in[5];   // [G, EPG, K]
    const float* b3       = (const float*)d_in[6];   // [G]
    const int*   edge     = (const int*)  d_in[7];   // [G, EPG]
    float*       out      = (float*)d_out;           // [B, G]

    prep_kernel<<<H2_BLOCKS + PACK_BLOCKS, BLKP>>>(
        features, (const float4*)w1, (const float4*)b1,
        (const float4*)w2, (const float4*)b2, edge, b3);

    cudaFuncSetAttribute(gather_kernel,
                         cudaFuncAttributeMaxDynamicSharedMemorySize, SMEM_TOTAL);

    // PDL launch: gather starts while prep drains; syncs on the grid
    // dependency before touching prep's outputs.
    cudaLaunchConfig_t cfg = {};
    cfg.gridDim = dim3(NSPLIT, NBT);
    cfg.blockDim = dim3(BLKG);
    cfg.dynamicSmemBytes = SMEM_TOTAL;
    cudaLaunchAttribute attrs[1];
    attrs[0].id = cudaLaunchAttributeProgrammaticStreamSerialization;
    attrs[0].val.programmaticStreamSerializationAllowed = 1;
    cfg.attrs = attrs;
    cfg.numAttrs = 1;
    cudaLaunchKernelEx(&cfg, gather_kernel, w3, out);
}

// round 12
// speedup vs baseline: 1.0602x; 1.0602x over previous
#include <cuda_runtime.h>
#include <cuda_fp16.h>
#include <cuda_pipeline.h>

#define T    512
#define K    4
#define G    20000
#define EPG  3
#define B    512

#define BT     32                  // batches per tile (= lanes)
#define NBT    (B / BT)            // 16
#define BLKG   1024                // 32 warps
#define GPB    256                 // g per chunk
#define CPS    9                   // chunks per split
#define NCHUNK 81                  // 81*256 = 20736; 9 splits x 9 chunks
#define GPAD   (NCHUNK * GPB)      // 20736
#define NSPLIT 9                   // grid 16*9 = 144 ~= 1 wave
#define BLKP   512                 // prep threads

// h2 fp16, layout [bt][t][b_in] as uint2 (k0k1, k2k3): 2 MB, L2-resident.
__device__ uint2  g_h2u[NBT * T * BT];
// per-g 16B record: {e0*32, e1*32, e2*32 (int bits), b3}
__device__ float4 g_q0[GPAD];

// SMEM (bytes): h2 128K | rec 2x16K (64B/g interleaved) | out 2x32K = 224K
#define S_H2   0
#define S_REC  131072
#define S_OUT  (131072 + 32768)
#define SMEM_TOTAL (131072 + 32768 + 65536)

__device__ __forceinline__ float leaky(float x) {
    return x > 0.0f ? x : 0.01f * x;
}

// Packed f32x2 FMA (Blackwell FFMA2) — bit-identical to two scalar fp32 FMAs.
__device__ __forceinline__ float2 ffma2(float2 a, float2 b, float2 c) {
    float2 d;
    asm("{\n\t"
        ".reg .b64 ra, rb, rc, rd;\n\t"
        "mov.b64 ra, {%2, %3};\n\t"
        "mov.b64 rb, {%4, %5};\n\t"
        "mov.b64 rc, {%6, %7};\n\t"
        "fma.rn.f32x2 rd, ra, rb, rc;\n\t"
        "mov.b64 {%0, %1}, rd;\n\t"
        "}"
        : "=f"(d.x), "=f"(d.y)
        : "f"(a.x), "f"(a.y), "f"(b.x), "f"(b.y), "f"(c.x), "f"(c.y));
    return d;
}

// ---------------------------------------------------------------------------
// Prep: blocks [0,512) compute h2; blocks [512, 512+41) pack q0 records.
// ---------------------------------------------------------------------------
#define H2_BLOCKS   512
#define PACK_BLOCKS ((GPAD + BLKP - 1) / BLKP)   // 41

__global__ void prep_kernel(const float*  __restrict__ features,
                            const float4* __restrict__ w1,
                            const float4* __restrict__ b1,
                            const float4* __restrict__ w2,
                            const float4* __restrict__ b2,
                            const int*    __restrict__ edge,
                            const float*  __restrict__ b3) {
    const int tid = threadIdx.x;
    if (blockIdx.x < H2_BLOCKS) {
        const int b_in = tid & 31;
        const int ty   = tid >> 5;
        const int bt   = blockIdx.x & (NBT - 1);
        const int t    = (blockIdx.x >> 4) * 16 + ty;
        const int b    = bt * BT + b_in;

        const float  f   = features[b * T + t];
        const float4 w1v = w1[t];
        const float4 b1v = b1[t];
        const float4 b2v = b2[t];

        const float h0 = leaky(fmaf(f, w1v.x, b1v.x));
        const float h1 = leaky(fmaf(f, w1v.y, b1v.y));
        const float h2 = leaky(fmaf(f, w1v.z, b1v.z));
        const float h3 = leaky(fmaf(f, w1v.w, b1v.w));

        const float4 w20 = w2[t * 4 + 0];
        const float4 w21 = w2[t * 4 + 1];
        const float4 w22 = w2[t * 4 + 2];
        const float4 w23 = w2[t * 4 + 3];

        float4 o;
        o.x = leaky(fmaf(h3, w23.x, fmaf(h2, w22.x, fmaf(h1, w21.x, fmaf(h0, w20.x, b2v.x)))));
        o.y = leaky(fmaf(h3, w23.y, fmaf(h2, w22.y, fmaf(h1, w21.y, fmaf(h0, w20.y, b2v.y)))));
        o.z = leaky(fmaf(h3, w23.z, fmaf(h2, w22.z, fmaf(h1, w21.z, fmaf(h0, w20.z, b2v.z)))));
        o.w = leaky(fmaf(h3, w23.w, fmaf(h2, w22.w, fmaf(h1, w21.w, fmaf(h0, w20.w, b2v.w)))));

        const __half2 p0 = __floats2half2_rn(o.x, o.y);
        const __half2 p1 = __floats2half2_rn(o.z, o.w);
        uint2 p;
        p.x = *reinterpret_cast<const unsigned int*>(&p0);
        p.y = *reinterpret_cast<const unsigned int*>(&p1);
        g_h2u[((size_t)bt * T + t) * BT + b_in] = p;
    } else {
        const int g = (blockIdx.x - H2_BLOCKS) * BLKP + tid;
        if (g >= GPAD) return;
        float4 q = make_float4(0.f, 0.f, 0.f, 0.f);
        if (g < G) {
            q = make_float4(__int_as_float(edge[3 * g + 0] * BT),
                            __int_as_float(edge[3 * g + 1] * BT),
                            __int_as_float(edge[3 * g + 2] * BT),
                            b3[g]);
        }
        g_q0[g] = q;
    }
}

// Stage one chunk's w3 into interleaved record slots rec[g*4 + 1..3].
__device__ __forceinline__ void stage_w3(float4* rec, const float* w3,
                                         int c, int tid) {
    const int nvg = min(GPB, max(0, G - c * GPB));
    const float4* wsrc = reinterpret_cast<const float4*>(w3 + (size_t)c * GPB * 12);
    if (tid < GPB * 3) {
        if (tid < nvg * 3) {
            const int g = tid / 3, part = tid - g * 3;
            __pipeline_memcpy_async(&rec[g * 4 + 1 + part], &wsrc[tid], 16);
        }
    }
}
// Stage one chunk's q0 into rec[g*4 + 0].
__device__ __forceinline__ void stage_q0(float4* rec, int c, int tid) {
    const int nvg = min(GPB, max(0, G - c * GPB));
    if (tid >= GPB * 3 && tid < GPB * 3 + GPB) {
        const int g = tid - GPB * 3;
        if (g < nvg)
            __pipeline_memcpy_async(&rec[g * 4], &g_q0[(size_t)c * GPB + g], 16);
    }
}

// ---------------------------------------------------------------------------
// Gather: persistent h2 tile, half-warp g-pairing, double-buffered {rec,s_out},
// one block barrier per chunk, PDL prologue, pipelined pair chain.
// ---------------------------------------------------------------------------
__global__ void __launch_bounds__(BLKG, 1)
gather_kernel(const float* __restrict__ w3, float* __restrict__ out) {
    extern __shared__ char sm[];
    uint2*  s_h2  = reinterpret_cast<uint2*>(sm + S_H2);     // [T*BT]
    float4* s_rec = reinterpret_cast<float4*>(sm + S_REC);   // [2][GPB*4]
    float*  s_out = reinterpret_cast<float*>(sm + S_OUT);    // [2][GPB*32]

    const int tid  = threadIdx.x;
    const int bt   = blockIdx.y;
    const int w    = tid >> 5;
    const int lane = tid & 31;
    const int half = lane >> 4;     // 0 or 1: which g of the pair
    const int hb   = lane & 15;     // batch within half

    int c = blockIdx.x;   // first chunk for this split

    // PDL: w3 is a kernel input (independent of prep) — stage it while prep runs.
    stage_w3(s_rec, w3, c, tid);
    __pipeline_commit();

    cudaGridDependencySynchronize();   // wait for prep grid (h2 + q0 ready)

    // Stage persistent h2 tile + first chunk's q0.
    {
        const uint4* src = reinterpret_cast<const uint4*>(g_h2u + (size_t)bt * T * BT);
        uint4*       dst = reinterpret_cast<uint4*>(s_h2);
        #pragma unroll
        for (int i = tid; i < T * BT / 2; i += BLKG)
            __pipeline_memcpy_async(&dst[i], &src[i], 16);
    }
    stage_q0(s_rec, c, tid);
    __pipeline_commit();
    __pipeline_wait_prior(0);
    __syncthreads();

    const int rotl = ((lane & 1) << 4) | ((lane >> 1) & 15);   // writeout swizzle

    #pragma unroll 1
    for (int iter = 0; iter < CPS; iter++) {
        const int  buf      = iter & 1;
        const bool has_next = (iter + 1 < CPS);

        // Prefetch next chunk into the other buffer (overlaps compute below).
        if (has_next) {
            const int cn = c + NSPLIT;
            float4* rdst = s_rec + (buf ^ 1) * (GPB * 4);
            stage_w3(rdst, w3, cn, tid);
            stage_q0(rdst, cn, tid);
            __pipeline_commit();
        }

        // Compute (skip fully-empty tail chunks): warp w owns 8 g as 4
        // half-warp pairs. Pipeline: next pair's q0 + all 6 h2 loads hoisted.
        if (c * GPB < G) {
            const float4* rec = s_rec + buf * (GPB * 4);
            float*        ob  = s_out + buf * (GPB * 32);
            const int gl0 = w * 8;

            // Pair-0 head: q0 + h2 rows for both b-passes.
            float4 q0 = rec[(gl0 + half) * 4];
            uint2 pa0 = s_h2[__float_as_int(q0.x) + hb];
            uint2 pa1 = s_h2[__float_as_int(q0.y) + hb];
            uint2 pa2 = s_h2[__float_as_int(q0.z) + hb];
            uint2 pb0 = s_h2[__float_as_int(q0.x) + hb + 16];
            uint2 pb1 = s_h2[__float_as_int(q0.y) + hb + 16];
            uint2 pb2 = s_h2[__float_as_int(q0.z) + hb + 16];

            #pragma unroll
            for (int pp = 0; pp < 4; pp++) {
                const int gsel = gl0 + 2 * pp + half;
                const int rot  = ((gsel & 1) << 4) | ((gsel >> 1) & 15);

                const float bias = q0.w;
                const uint2 c0 = pa0, c1 = pa1, c2 = pa2;
                const uint2 d0 = pb0, d1 = pb1, d2 = pb2;

                // Prefetch next pair's head while this pair's FMAs run.
                if (pp < 3) {
                    q0 = rec[(gsel + 2) * 4];
                    pa0 = s_h2[__float_as_int(q0.x) + hb];
                    pa1 = s_h2[__float_as_int(q0.y) + hb];
                    pa2 = s_h2[__float_as_int(q0.z) + hb];
                    pb0 = s_h2[__float_as_int(q0.x) + hb + 16];
                    pb1 = s_h2[__float_as_int(q0.y) + hb + 16];
                    pb2 = s_h2[__float_as_int(q0.z) + hb + 16];
                }

                const float4 q1 = rec[gsel * 4 + 1];
                const float4 q2 = rec[gsel * 4 + 2];
                const float4 q3 = rec[gsel * 4 + 3];

                // pass 0: b = hb
                {
                    float2 acc0 = make_float2(bias, 0.f);
                    float2 acc1 = make_float2(0.f, 0.f);
                    acc0 = ffma2(__half22float2(*reinterpret_cast<const __half2*>(&c0.x)),
                                 make_float2(q1.x, q1.y), acc0);
                    acc1 = ffma2(__half22float2(*reinterpret_cast<const __half2*>(&c0.y)),
                                 make_float2(q1.z, q1.w), acc1);
                    acc0 = ffma2(__half22float2(*reinterpret_cast<const __half2*>(&c1.x)),
                                 make_float2(q2.x, q2.y), acc0);
                    acc1 = ffma2(__half22float2(*reinterpret_cast<const __half2*>(&c1.y)),
                                 make_float2(q2.z, q2.w), acc1);
                    acc0 = ffma2(__half22float2(*reinterpret_cast<const __half2*>(&c2.x)),
                                 make_float2(q3.x, q3.y), acc0);
                    acc1 = ffma2(__half22float2(*reinterpret_cast<const __half2*>(&c2.y)),
                                 make_float2(q3.z, q3.w), acc1);
                    const float r = (acc0.x + acc1.x) + (acc0.y + acc1.y);
                    ob[gsel * 32 + (hb ^ rot)] = r;
                }
                // pass 1: b = hb + 16
                {
                    float2 acc0 = make_float2(bias, 0.f);
                    float2 acc1 = make_float2(0.f, 0.f);
                    acc0 = ffma2(__half22float2(*reinterpret_cast<const __half2*>(&d0.x)),
                                 make_float2(q1.x, q1.y), acc0);
                    acc1 = ffma2(__half22float2(*reinterpret_cast<const __half2*>(&d0.y)),
                                 make_float2(q1.z, q1.w), acc1);
                    acc0 = ffma2(__half22float2(*reinterpret_cast<const __half2*>(&d1.x)),
                                 make_float2(q2.x, q2.y), acc0);
                    acc1 = ffma2(__half22float2(*reinterpret_cast<const __half2*>(&d1.y)),
                                 make_float2(q2.z, q2.w), acc1);
                    acc0 = ffma2(__half22float2(*reinterpret_cast<const __half2*>(&d2.x)),
                                 make_float2(q3.x, q3.y), acc0);
                    acc1 = ffma2(__half22float2(*reinterpret_cast<const __half2*>(&d2.y)),
                                 make_float2(q3.z, q3.w), acc1);
                    const float r = (acc0.x + acc1.x) + (acc0.y + acc1.y);
                    ob[gsel * 32 + ((hb + 16) ^ rot)] = r;
                }
            }
        }

        // ONE barrier: publishes s_out[buf]; next compute uses s_out[buf^1].
        __syncthreads();

        // Coalesced write-out: warp = batch row, lane = consecutive g (128B STG).
        {
            const float* ob = s_out + buf * (GPB * 32);
            const int gbase = c * GPB;
            float* orow = out + (size_t)(bt * BT + w) * G + gbase;
            #pragma unroll
            for (int it2 = 0; it2 < 8; it2++) {
                const int gl = it2 * 32 + lane;
                if (gbase + gl < G)
                    orow[gl] = ob[gl * 32 + (w ^ rotl)];
            }
        }

        if (has_next) __pipeline_wait_prior(0);   // next rec resident
        c += NSPLIT;
    }
}

extern "C" void kernel_launch(void* const* d_in, const int* in_sizes, int n_in,
                              void* d_out, int out_size) {
    const float* features = (const float*)d_in[0];   // [B, T]
    const float* w1       = (const float*)d_in[1];   // [T, K]
    const float* b1       = (const float*)d_in[2];   // [T, K]
    const float* w2       = (const float*)d_in[3];   // [T, K, K]
    const float* b2       = (const float*)d_in[4];   // [T, K]
    const float* w3       = (const float*)d_in[5];   // [G, EPG, K]
    const float* b3       = (const float*)d_in[6];   // [G]
    const int*   edge     = (const int*)  d_in[7];   // [G, EPG]
    float*       out      = (float*)d_out;           // [B, G]

    prep_kernel<<<H2_BLOCKS + PACK_BLOCKS, BLKP>>>(
        features, (const float4*)w1, (const float4*)b1,
        (const float4*)w2, (const float4*)b2, edge, b3);

    cudaFuncSetAttribute(gather_kernel,
                         cudaFuncAttributeMaxDynamicSharedMemorySize, SMEM_TOTAL);

    // PDL launch: gather may start while prep drains; it syncs on the grid
    // dependency before touching prep's outputs.
    cudaLaunchConfig_t cfg = {};
    cfg.gridDim = dim3(NSPLIT, NBT);
    cfg.blockDim = dim3(BLKG);
    cfg.dynamicSmemBytes = SMEM_TOTAL;
    cudaLaunchAttribute attrs[1];
    attrs[0].id = cudaLaunchAttributeProgrammaticStreamSerialization;
    attrs[0].val.programmaticStreamSerializationAllowed = 1;
    cfg.attrs = attrs;
    cfg.numAttrs = 1;
    cudaLaunchKernelEx(&cfg, gather_kernel, w3, out);
}

// round 13
// speedup vs baseline: 1.1373x; 1.0727x over previous
#include <cuda_runtime.h>
#include <cuda_fp16.h>
#include <cuda_pipeline.h>

#define T    512
#define K    4
#define G    20000
#define EPG  3
#define B    512

#define BT     32                  // batches per tile (= lanes)
#define NBT    (B / BT)            // 16
#define BLKG   1024                // 32 warps
#define GPB    256                 // g per chunk
#define CPS    9                   // chunks per split
#define NCHUNK 81                  // 81*256 = 20736; 9 splits x 9 chunks
#define GPAD   (NCHUNK * GPB)      // 20736
#define NSPLIT 9                   // grid 16*9 = 144 ~= 1 wave
#define BLKP   512                 // prep threads

// h2 fp16, layout [bt][t][b_in] as uint2 (k0k1, k2k3): 2 MB, L2-resident.
__device__ uint2  g_h2u[NBT * T * BT];
// per-g 16B record: {e0*16, e1*16, e2*16 (int bits, uint4-index scale), b3}
__device__ float4 g_q0[GPAD];

// SMEM (bytes): h2 128K | rec 2x16K (64B/g interleaved) | out 2x32K = 224K
#define S_H2   0
#define S_REC  131072
#define S_OUT  (131072 + 32768)
#define SMEM_TOTAL (131072 + 32768 + 65536)

__device__ __forceinline__ float leaky(float x) {
    return x > 0.0f ? x : 0.01f * x;
}

// Packed f32x2 FMA (Blackwell FFMA2) — bit-identical to two scalar fp32 FMAs.
__device__ __forceinline__ float2 ffma2(float2 a, float2 b, float2 c) {
    float2 d;
    asm("{\n\t"
        ".reg .b64 ra, rb, rc, rd;\n\t"
        "mov.b64 ra, {%2, %3};\n\t"
        "mov.b64 rb, {%4, %5};\n\t"
        "mov.b64 rc, {%6, %7};\n\t"
        "fma.rn.f32x2 rd, ra, rb, rc;\n\t"
        "mov.b64 {%0, %1}, rd;\n\t"
        "}"
        : "=f"(d.x), "=f"(d.y)
        : "f"(a.x), "f"(a.y), "f"(b.x), "f"(b.y), "f"(c.x), "f"(c.y));
    return d;
}

// ---------------------------------------------------------------------------
// Prep: blocks [0,512) compute h2; blocks [512, 512+41) pack q0 records.
// ---------------------------------------------------------------------------
#define H2_BLOCKS   512
#define PACK_BLOCKS ((GPAD + BLKP - 1) / BLKP)   // 41

__global__ void prep_kernel(const float*  __restrict__ features,
                            const float4* __restrict__ w1,
                            const float4* __restrict__ b1,
                            const float4* __restrict__ w2,
                            const float4* __restrict__ b2,
                            const int*    __restrict__ edge,
                            const float*  __restrict__ b3) {
    const int tid = threadIdx.x;
    if (blockIdx.x < H2_BLOCKS) {
        const int b_in = tid & 31;
        const int ty   = tid >> 5;
        const int bt   = blockIdx.x & (NBT - 1);
        const int t    = (blockIdx.x >> 4) * 16 + ty;
        const int b    = bt * BT + b_in;

        const float  f   = features[b * T + t];
        const float4 w1v = w1[t];
        const float4 b1v = b1[t];
        const float4 b2v = b2[t];

        const float h0 = leaky(fmaf(f, w1v.x, b1v.x));
        const float h1 = leaky(fmaf(f, w1v.y, b1v.y));
        const float h2 = leaky(fmaf(f, w1v.z, b1v.z));
        const float h3 = leaky(fmaf(f, w1v.w, b1v.w));

        const float4 w20 = w2[t * 4 + 0];
        const float4 w21 = w2[t * 4 + 1];
        const float4 w22 = w2[t * 4 + 2];
        const float4 w23 = w2[t * 4 + 3];

        float4 o;
        o.x = leaky(fmaf(h3, w23.x, fmaf(h2, w22.x, fmaf(h1, w21.x, fmaf(h0, w20.x, b2v.x)))));
        o.y = leaky(fmaf(h3, w23.y, fmaf(h2, w22.y, fmaf(h1, w21.y, fmaf(h0, w20.y, b2v.y)))));
        o.z = leaky(fmaf(h3, w23.z, fmaf(h2, w22.z, fmaf(h1, w21.z, fmaf(h0, w20.z, b2v.z)))));
        o.w = leaky(fmaf(h3, w23.w, fmaf(h2, w22.w, fmaf(h1, w21.w, fmaf(h0, w20.w, b2v.w)))));

        const __half2 p0 = __floats2half2_rn(o.x, o.y);
        const __half2 p1 = __floats2half2_rn(o.z, o.w);
        uint2 p;
        p.x = *reinterpret_cast<const unsigned int*>(&p0);
        p.y = *reinterpret_cast<const unsigned int*>(&p1);
        g_h2u[((size_t)bt * T + t) * BT + b_in] = p;
    } else {
        const int g = (blockIdx.x - H2_BLOCKS) * BLKP + tid;
        if (g >= GPAD) return;
        float4 q = make_float4(0.f, 0.f, 0.f, 0.f);
        if (g < G) {
            // scale = 16: index into uint4-view of the h2 tile (t*16 + hb)
            q = make_float4(__int_as_float(edge[3 * g + 0] * 16),
                            __int_as_float(edge[3 * g + 1] * 16),
                            __int_as_float(edge[3 * g + 2] * 16),
                            b3[g]);
        }
        g_q0[g] = q;
    }
}

// Stage one chunk's w3 into interleaved record slots rec[g*4 + 1..3].
__device__ __forceinline__ void stage_w3(float4* rec, const float* w3,
                                         int c, int tid) {
    const int nvg = min(GPB, max(0, G - c * GPB));
    const float4* wsrc = reinterpret_cast<const float4*>(w3 + (size_t)c * GPB * 12);
    if (tid < GPB * 3) {
        if (tid < nvg * 3) {
            const int g = tid / 3, part = tid - g * 3;
            __pipeline_memcpy_async(&rec[g * 4 + 1 + part], &wsrc[tid], 16);
        }
    }
}
// Stage one chunk's q0 into rec[g*4 + 0].
__device__ __forceinline__ void stage_q0(float4* rec, int c, int tid) {
    const int nvg = min(GPB, max(0, G - c * GPB));
    if (tid >= GPB * 3 && tid < GPB * 3 + GPB) {
        const int g = tid - GPB * 3;
        if (g < nvg)
            __pipeline_memcpy_async(&rec[g * 4], &g_q0[(size_t)c * GPB + g], 16);
    }
}

// ---------------------------------------------------------------------------
// Gather: persistent h2 tile, half-warp g-pairing, single-pass uint4 h2 loads
// (lane = 2 batches), double-buffered {rec, s_out}, one barrier/chunk, PDL.
// ---------------------------------------------------------------------------
__global__ void __launch_bounds__(BLKG, 1)
gather_kernel(const float* __restrict__ w3, float* __restrict__ out) {
    extern __shared__ char sm[];
    const uint4* s_h2q = reinterpret_cast<const uint4*>(sm + S_H2);  // [T*16]
    float4*      s_rec = reinterpret_cast<float4*>(sm + S_REC);      // [2][GPB*4]
    float*       s_out = reinterpret_cast<float*>(sm + S_OUT);       // [2][GPB*32]

    const int tid  = threadIdx.x;
    const int bt   = blockIdx.y;
    const int w    = tid >> 5;
    const int lane = tid & 31;
    const int half = lane >> 4;     // 0 or 1: which g of the pair
    const int hb   = lane & 15;     // batch-pair index: covers b = 2hb, 2hb+1

    int c = blockIdx.x;   // first chunk for this split

    // PDL: w3 is a kernel input (independent of prep) — stage while prep runs.
    stage_w3(s_rec, w3, c, tid);
    __pipeline_commit();

    cudaGridDependencySynchronize();   // prep grid done (h2 + q0 ready)

    // Stage persistent h2 tile + first chunk's q0.
    {
        const uint4* src = reinterpret_cast<const uint4*>(g_h2u + (size_t)bt * T * BT);
        uint4*       dst = reinterpret_cast<uint4*>(sm + S_H2);
        #pragma unroll
        for (int i = tid; i < T * BT / 2; i += BLKG)
            __pipeline_memcpy_async(&dst[i], &src[i], 16);
    }
    stage_q0(s_rec, c, tid);
    __pipeline_commit();
    __pipeline_wait_prior(0);
    __syncthreads();

    #pragma unroll 1
    for (int iter = 0; iter < CPS; iter++) {
        const int  buf      = iter & 1;
        const bool has_next = (iter + 1 < CPS);

        // Prefetch next chunk into the other buffer (overlaps compute below).
        if (has_next) {
            const int cn = c + NSPLIT;
            float4* rdst = s_rec + (buf ^ 1) * (GPB * 4);
            stage_w3(rdst, w3, cn, tid);
            stage_q0(rdst, cn, tid);
            __pipeline_commit();
        }

        // Compute: warp w owns 8 g as 4 half-warp pairs, single pass:
        // each lane serves batches 2hb and 2hb+1 via uint4 h2 loads.
        {
            const float4* rec = s_rec + buf * (GPB * 4);
            float*        ob  = s_out + buf * (GPB * 32);
            const int gl0 = w * 8;

            #pragma unroll
            for (int pp = 0; pp < 4; pp++) {
                const int gsel = gl0 + 2 * pp + half;
                const int xs   = gsel & 31;      // xor swizzle column key

                // One LDS.128 wavefront serves both halves (banks disjoint).
                const float4 q0 = rec[gsel * 4 + 0];
                const float4 q1 = rec[gsel * 4 + 1];
                const float4 q2 = rec[gsel * 4 + 2];
                const float4 q3 = rec[gsel * 4 + 3];

                // 3 h2 LDS.128: {b0.k01, b0.k23, b1.k01, b1.k23}
                const uint4 h0 = s_h2q[__float_as_int(q0.x) + hb];
                const uint4 h1 = s_h2q[__float_as_int(q0.y) + hb];
                const uint4 h2 = s_h2q[__float_as_int(q0.z) + hb];

                // 4 independent accumulator chains (2 per batch).
                float2 a00 = make_float2(q0.w, 0.f), a01 = make_float2(0.f, 0.f);
                float2 a10 = make_float2(q0.w, 0.f), a11 = make_float2(0.f, 0.f);

                a00 = ffma2(__half22float2(*reinterpret_cast<const __half2*>(&h0.x)),
                            make_float2(q1.x, q1.y), a00);
                a01 = ffma2(__half22float2(*reinterpret_cast<const __half2*>(&h0.y)),
                            make_float2(q1.z, q1.w), a01);
                a10 = ffma2(__half22float2(*reinterpret_cast<const __half2*>(&h0.z)),
                            make_float2(q1.x, q1.y), a10);
                a11 = ffma2(__half22float2(*reinterpret_cast<const __half2*>(&h0.w)),
                            make_float2(q1.z, q1.w), a11);

                a00 = ffma2(__half22float2(*reinterpret_cast<const __half2*>(&h1.x)),
                            make_float2(q2.x, q2.y), a00);
                a01 = ffma2(__half22float2(*reinterpret_cast<const __half2*>(&h1.y)),
                            make_float2(q2.z, q2.w), a01);
                a10 = ffma2(__half22float2(*reinterpret_cast<const __half2*>(&h1.z)),
                            make_float2(q2.x, q2.y), a10);
                a11 = ffma2(__half22float2(*reinterpret_cast<const __half2*>(&h1.w)),
                            make_float2(q2.z, q2.w), a11);

                a00 = ffma2(__half22float2(*reinterpret_cast<const __half2*>(&h2.x)),
                            make_float2(q3.x, q3.y), a00);
                a01 = ffma2(__half22float2(*reinterpret_cast<const __half2*>(&h2.y)),
                            make_float2(q3.z, q3.w), a01);
                a10 = ffma2(__half22float2(*reinterpret_cast<const __half2*>(&h2.z)),
                            make_float2(q3.x, q3.y), a10);
                a11 = ffma2(__half22float2(*reinterpret_cast<const __half2*>(&h2.w)),
                            make_float2(q3.z, q3.w), a11);

                const float r0 = (a00.x + a01.x) + (a00.y + a01.y);
                const float r1 = (a10.x + a11.x) + (a10.y + a11.y);

                // xor swizzle: per instruction halves land on disjoint bank
                // parity classes (xs_b = xs_a ^ 1) -> 1 wavefront per STS.
                ob[gsel * 32 + ((2 * hb)     ^ xs)] = r0;
                ob[gsel * 32 + ((2 * hb + 1) ^ xs)] = r1;
            }
        }

        // ONE barrier: publishes s_out[buf]; next compute uses s_out[buf^1].
        __syncthreads();

        // Coalesced write-out: warp = batch row, lane = consecutive g (128B STG).
        {
            const float* ob = s_out + buf * (GPB * 32);
            const int gbase = c * GPB;
            float* orow = out + (size_t)(bt * BT + w) * G + gbase;
            #pragma unroll
            for (int it2 = 0; it2 < 8; it2++) {
                const int gl = it2 * 32 + lane;
                if (gbase + gl < G)
                    orow[gl] = ob[gl * 32 + (w ^ lane)];
            }
        }

        if (has_next) __pipeline_wait_prior(0);   // next rec resident
        c += NSPLIT;
    }
}

extern "C" void kernel_launch(void* const* d_in, const int* in_sizes, int n_in,
                              void* d_out, int out_size) {
    const float* features = (const float*)d_in[0];   // [B, T]
    const float* w1       = (const float*)d_in[1];   // [T, K]
    const float* b1       = (const float*)d_in[2];   // [T, K]
    const float* w2       = (const float*)d_in[3];   // [T, K, K]
    const float* b2       = (const float*)d_in[4];   // [T, K]
    const float* w3       = (const float*)d_in[5];   // [G, EPG, K]
    const float* b3       = (const float*)d_in[6];   // [G]
    const int*   edge     = (const int*)  d_in[7];   // [G, EPG]
    float*       out      = (float*)d_out;           // [B, G]

    prep_kernel<<<H2_BLOCKS + PACK_BLOCKS, BLKP>>>(
        features, (const float4*)w1, (const float4*)b1,
        (const float4*)w2, (const float4*)b2, edge, b3);

    cudaFuncSetAttribute(gather_kernel,
                         cudaFuncAttributeMaxDynamicSharedMemorySize, SMEM_TOTAL);

    // PDL launch: gather may start while prep drains; it syncs on the grid
    // dependency before touching prep's outputs.
    cudaLaunchConfig_t cfg = {};
    cfg.gridDim = dim3(NSPLIT, NBT);
    cfg.blockDim = dim3(BLKG);
    cfg.dynamicSmemBytes = SMEM_TOTAL;
    cudaLaunchAttribute attrs[1];
    attrs[0].id = cudaLaunchAttributeProgrammaticStreamSerialization;
    attrs[0].val.programmaticStreamSerializationAllowed = 1;
    cfg.attrs = attrs;
    cfg.numAttrs = 1;
    cudaLaunchKernelEx(&cfg, gather_kernel, w3, out);
}

// round 14
// speedup vs baseline: 1.2065x; 1.0609x over previous
#include <cuda_runtime.h>
#include <cuda_fp16.h>
#include <cuda_pipeline.h>

#define T    512
#define K    4
#define G    20000
#define EPG  3
#define B    512

#define BT     32                  // batches per tile (= lanes)
#define NBT    (B / BT)            // 16
#define BLKG   1024                // 32 warps = 2 groups of 16
#define GPB    256                 // g per super-chunk (128 per group)
#define GPG    128                 // g per group-chunk
#define CPS    9                   // chunks per split
#define NCHUNK 81                  // 81*256 = 20736; 9 splits x 9 chunks
#define GPAD   (NCHUNK * GPB)      // 20736
#define NSPLIT 9                   // grid 16*9 = 144 ~= 1 wave
#define BLKP   512                 // prep threads

// h2 fp16, layout [bt][t][b_in] as uint2 (k0k1, k2k3): 2 MB, L2-resident.
__device__ uint2  g_h2u[NBT * T * BT];
// per-g 16B record: {e0*16, e1*16, e2*16 (int bits, uint4-index scale), b3}
__device__ float4 g_q0[GPAD];

// SMEM (bytes): h2 128K | rec 2 groups x 2 bufs x 8K | out 2 x 2 x 16K = 224K
#define S_H2   0
#define S_REC  131072                    // + gid*16384 + buf*8192
#define S_OUT  (131072 + 32768)          // + gid*32768 + buf*16384
#define SMEM_TOTAL (131072 + 32768 + 65536)

__device__ __forceinline__ float leaky(float x) {
    return x > 0.0f ? x : 0.01f * x;
}

// Packed f32x2 FMA (Blackwell FFMA2) — bit-identical to two scalar fp32 FMAs.
__device__ __forceinline__ float2 ffma2(float2 a, float2 b, float2 c) {
    float2 d;
    asm("{\n\t"
        ".reg .b64 ra, rb, rc, rd;\n\t"
        "mov.b64 ra, {%2, %3};\n\t"
        "mov.b64 rb, {%4, %5};\n\t"
        "mov.b64 rc, {%6, %7};\n\t"
        "fma.rn.f32x2 rd, ra, rb, rc;\n\t"
        "mov.b64 {%0, %1}, rd;\n\t"
        "}"
        : "=f"(d.x), "=f"(d.y)
        : "f"(a.x), "f"(a.y), "f"(b.x), "f"(b.y), "f"(c.x), "f"(c.y));
    return d;
}

// ---------------------------------------------------------------------------
// Prep: blocks [0,512) compute h2; blocks [512, 512+41) pack q0 records.
// ---------------------------------------------------------------------------
#define H2_BLOCKS   512
#define PACK_BLOCKS ((GPAD + BLKP - 1) / BLKP)   // 41

__global__ void prep_kernel(const float*  __restrict__ features,
                            const float4* __restrict__ w1,
                            const float4* __restrict__ b1,
                            const float4* __restrict__ w2,
                            const float4* __restrict__ b2,
                            const int*    __restrict__ edge,
                            const float*  __restrict__ b3) {
    const int tid = threadIdx.x;
    if (blockIdx.x < H2_BLOCKS) {
        const int b_in = tid & 31;
        const int ty   = tid >> 5;
        const int bt   = blockIdx.x & (NBT - 1);
        const int t    = (blockIdx.x >> 4) * 16 + ty;
        const int b    = bt * BT + b_in;

        const float  f   = features[b * T + t];
        const float4 w1v = w1[t];
        const float4 b1v = b1[t];
        const float4 b2v = b2[t];

        const float h0 = leaky(fmaf(f, w1v.x, b1v.x));
        const float h1 = leaky(fmaf(f, w1v.y, b1v.y));
        const float h2 = leaky(fmaf(f, w1v.z, b1v.z));
        const float h3 = leaky(fmaf(f, w1v.w, b1v.w));

        const float4 w20 = w2[t * 4 + 0];
        const float4 w21 = w2[t * 4 + 1];
        const float4 w22 = w2[t * 4 + 2];
        const float4 w23 = w2[t * 4 + 3];

        float4 o;
        o.x = leaky(fmaf(h3, w23.x, fmaf(h2, w22.x, fmaf(h1, w21.x, fmaf(h0, w20.x, b2v.x)))));
        o.y = leaky(fmaf(h3, w23.y, fmaf(h2, w22.y, fmaf(h1, w21.y, fmaf(h0, w20.y, b2v.y)))));
        o.z = leaky(fmaf(h3, w23.z, fmaf(h2, w22.z, fmaf(h1, w21.z, fmaf(h0, w20.z, b2v.z)))));
        o.w = leaky(fmaf(h3, w23.w, fmaf(h2, w22.w, fmaf(h1, w21.w, fmaf(h0, w20.w, b2v.w)))));

        const __half2 p0 = __floats2half2_rn(o.x, o.y);
        const __half2 p1 = __floats2half2_rn(o.z, o.w);
        uint2 p;
        p.x = *reinterpret_cast<const unsigned int*>(&p0);
        p.y = *reinterpret_cast<const unsigned int*>(&p1);
        g_h2u[((size_t)bt * T + t) * BT + b_in] = p;
    } else {
        const int g = (blockIdx.x - H2_BLOCKS) * BLKP + tid;
        if (g >= GPAD) return;
        float4 q = make_float4(0.f, 0.f, 0.f, 0.f);
        if (g < G) {
            // scale = 16: index into uint4-view of the h2 tile (t*16 + hb)
            q = make_float4(__int_as_float(edge[3 * g + 0] * 16),
                            __int_as_float(edge[3 * g + 1] * 16),
                            __int_as_float(edge[3 * g + 2] * 16),
                            b3[g]);
        }
        g_q0[g] = q;
    }
}

// Stage one GROUP chunk (128 g): w3 (384 float4) + q0 (128), 512 threads.
__device__ __forceinline__ void stage_group(float4* rec, const float* w3,
                                            int go, int tg) {
    const int nvg = min(GPG, max(0, G - go));
    if (tg < GPG * 3) {
        if (tg < nvg * 3) {
            const float4* wsrc =
                reinterpret_cast<const float4*>(w3 + (size_t)go * 12);
            const int g = tg / 3, part = tg - g * 3;
            __pipeline_memcpy_async(&rec[g * 4 + 1 + part], &wsrc[tg], 16);
        }
    } else {
        const int g = tg - GPG * 3;   // 0..127
        if (g < nvg)
            __pipeline_memcpy_async(&rec[g * 4], &g_q0[(size_t)go + g], 16);
    }
}

// ---------------------------------------------------------------------------
// Gather: persistent shared h2 tile; TWO independent 16-warp pipeline groups
// (own rec/out double-buffers, own named barrier) — decoupled chunk cadence.
// ---------------------------------------------------------------------------
__global__ void __launch_bounds__(BLKG, 1)
gather_kernel(const float* __restrict__ w3, float* __restrict__ out) {
    extern __shared__ char sm[];
    const uint4* s_h2q = reinterpret_cast<const uint4*>(sm + S_H2);  // [T*16]

    const int tid  = threadIdx.x;
    const int bt   = blockIdx.y;
    const int w    = tid >> 5;
    const int lane = tid & 31;
    const int gid  = w >> 4;        // pipeline group 0/1
    const int wg   = w & 15;        // warp within group
    const int tg   = tid & 511;     // thread within group
    const int half = lane >> 4;     // which g of the pair
    const int hb   = lane & 15;     // batch-pair index: covers b = 2hb, 2hb+1

    float4* g_rec = reinterpret_cast<float4*>(sm + S_REC + gid * 16384);
    float*  g_out = reinterpret_cast<float*>(sm + S_OUT + gid * 32768);

    int c = blockIdx.x;   // first super-chunk for this split

    // PDL: w3/q0-independent staging while prep drains? w3 is an input —
    // stage group's first chunk of it now.
    {
        const int go = c * GPB + gid * GPG;
        const int nvg = min(GPG, max(0, G - go));
        if (tg < nvg * 3) {
            const float4* wsrc =
                reinterpret_cast<const float4*>(w3 + (size_t)go * 12);
            const int g = tg / 3, part = tg - g * 3;
            __pipeline_memcpy_async(&g_rec[g * 4 + 1 + part], &wsrc[tg], 16);
        }
    }
    __pipeline_commit();

    cudaGridDependencySynchronize();   // prep grid done (h2 + q0 ready)

    // Stage persistent h2 tile (all 1024 threads) + first chunk's q0.
    {
        const uint4* src = reinterpret_cast<const uint4*>(g_h2u + (size_t)bt * T * BT);
        uint4*       dst = reinterpret_cast<uint4*>(sm + S_H2);
        #pragma unroll
        for (int i = tid; i < T * BT / 2; i += BLKG)
            __pipeline_memcpy_async(&dst[i], &src[i], 16);
    }
    {
        const int go = c * GPB + gid * GPG;
        const int nvg = min(GPG, max(0, G - go));
        if (tg >= GPG * 3) {
            const int g = tg - GPG * 3;
            if (g < nvg)
                __pipeline_memcpy_async(&g_rec[g * 4], &g_q0[(size_t)go + g], 16);
        }
    }
    __pipeline_commit();
    __pipeline_wait_prior(0);
    __syncthreads();   // h2 tile published to the whole block

    const int barid = 1 + gid;

    #pragma unroll 1
    for (int iter = 0; iter < CPS; iter++) {
        const int  buf      = iter & 1;
        const bool has_next = (iter + 1 < CPS);

        // Prefetch group's next chunk into the other buffer.
        if (has_next) {
            stage_group(g_rec + (buf ^ 1) * (GPG * 4), w3,
                        (c + NSPLIT) * GPB + gid * GPG, tg);
            __pipeline_commit();
        }

        // Compute: warp wg owns 8 g as 4 half-warp pairs, single pass:
        // each lane serves batches 2hb and 2hb+1 via uint4 h2 loads.
        {
            const float4* rec = g_rec + buf * (GPG * 4);
            float*        ob  = g_out + buf * (GPG * 32);
            const int gl0 = wg * 8;

            #pragma unroll
            for (int pp = 0; pp < 4; pp++) {
                const int gsel = gl0 + 2 * pp + half;
                const int xs   = gsel & 31;      // xor swizzle column key

                const float4 q0 = rec[gsel * 4 + 0];
                const float4 q1 = rec[gsel * 4 + 1];
                const float4 q2 = rec[gsel * 4 + 2];
                const float4 q3 = rec[gsel * 4 + 3];

                const uint4 h0 = s_h2q[__float_as_int(q0.x) + hb];
                const uint4 h1 = s_h2q[__float_as_int(q0.y) + hb];
                const uint4 h2 = s_h2q[__float_as_int(q0.z) + hb];

                float2 a00 = make_float2(q0.w, 0.f), a01 = make_float2(0.f, 0.f);
                float2 a10 = make_float2(q0.w, 0.f), a11 = make_float2(0.f, 0.f);

                a00 = ffma2(__half22float2(*reinterpret_cast<const __half2*>(&h0.x)),
                            make_float2(q1.x, q1.y), a00);
                a01 = ffma2(__half22float2(*reinterpret_cast<const __half2*>(&h0.y)),
                            make_float2(q1.z, q1.w), a01);
                a10 = ffma2(__half22float2(*reinterpret_cast<const __half2*>(&h0.z)),
                            make_float2(q1.x, q1.y), a10);
                a11 = ffma2(__half22float2(*reinterpret_cast<const __half2*>(&h0.w)),
                            make_float2(q1.z, q1.w), a11);

                a00 = ffma2(__half22float2(*reinterpret_cast<const __half2*>(&h1.x)),
                            make_float2(q2.x, q2.y), a00);
                a01 = ffma2(__half22float2(*reinterpret_cast<const __half2*>(&h1.y)),
                            make_float2(q2.z, q2.w), a01);
                a10 = ffma2(__half22float2(*reinterpret_cast<const __half2*>(&h1.z)),
                            make_float2(q2.x, q2.y), a10);
                a11 = ffma2(__half22float2(*reinterpret_cast<const __half2*>(&h1.w)),
                            make_float2(q2.z, q2.w), a11);

                a00 = ffma2(__half22float2(*reinterpret_cast<const __half2*>(&h2.x)),
                            make_float2(q3.x, q3.y), a00);
                a01 = ffma2(__half22float2(*reinterpret_cast<const __half2*>(&h2.y)),
                            make_float2(q3.z, q3.w), a01);
                a10 = ffma2(__half22float2(*reinterpret_cast<const __half2*>(&h2.z)),
                            make_float2(q3.x, q3.y), a10);
                a11 = ffma2(__half22float2(*reinterpret_cast<const __half2*>(&h2.w)),
                            make_float2(q3.z, q3.w), a11);

                const float r0 = (a00.x + a01.x) + (a00.y + a01.y);
                const float r1 = (a10.x + a11.x) + (a10.y + a11.y);

                ob[gsel * 32 + ((2 * hb)     ^ xs)] = r0;
                ob[gsel * 32 + ((2 * hb + 1) ^ xs)] = r1;
            }
        }

        // Staging for next chunk resident to THIS thread, then one GROUP
        // barrier publishes both s_out[buf] and the next rec buffer.
        if (has_next) __pipeline_wait_prior(0);
        asm volatile("bar.sync %0, %1;" :: "r"(barid), "r"(512) : "memory");

        // Coalesced write-out: warp wg covers batch rows wg and wg+16.
        {
            const float* ob = g_out + buf * (GPG * 32);
            const int gbase = c * GPB + gid * GPG;
            #pragma unroll
            for (int bh = 0; bh < 2; bh++) {
                const int b_local = wg + bh * 16;
                float* orow = out + (size_t)(bt * BT + b_local) * G + gbase;
                #pragma unroll
                for (int it2 = 0; it2 < 4; it2++) {
                    const int gl = it2 * 32 + lane;
                    if (gbase + gl < G)
                        orow[gl] = ob[gl * 32 + (b_local ^ (gl & 31))];
                }
            }
        }

        c += NSPLIT;
    }
}

extern "C" void kernel_launch(void* const* d_in, const int* in_sizes, int n_in,
                              void* d_out, int out_size) {
    const float* features = (const float*)d_in[0];   // [B, T]
    const float* w1       = (const float*)d_in[1];   // [T, K]
    const float* b1       = (const float*)d_in[2];   // [T, K]
    const float* w2       = (const float*)d_in[3];   // [T, K, K]
    const float* b2       = (const float*)d_in[4];   // [T, K]
    const float* w3       = (const float*)d_in[5];   // [G, EPG, K]
    const float* b3       = (const float*)d_in[6];   // [G]
    const int*   edge     = (const int*)  d_in[7];   // [G, EPG]
    float*       out      = (float*)d_out;           // [B, G]

    prep_kernel<<<H2_BLOCKS + PACK_BLOCKS, BLKP>>>(
        features, (const float4*)w1, (const float4*)b1,
        (const float4*)w2, (const float4*)b2, edge, b3);

    cudaFuncSetAttribute(gather_kernel,
                         cudaFuncAttributeMaxDynamicSharedMemorySize, SMEM_TOTAL);

    // PDL launch: gather may start while prep drains; it syncs on the grid
    // dependency before touching prep's outputs.
    cudaLaunchConfig_t cfg = {};
    cfg.gridDim = dim3(NSPLIT, NBT);
    cfg.blockDim = dim3(BLKG);
    cfg.dynamicSmemBytes = SMEM_TOTAL;
    cudaLaunchAttribute attrs[1];
    attrs[0].id = cudaLaunchAttributeProgrammaticStreamSerialization;
    attrs[0].val.programmaticStreamSerializationAllowed = 1;
    cfg.attrs = attrs;
    cfg.numAttrs = 1;
    cudaLaunchKernelEx(&cfg, gather_kernel, w3, out);
}

// round 15
// speedup vs baseline: 1.2092x; 1.0022x over previous
#include <cuda_runtime.h>
#include <cuda_fp16.h>
#include <cuda_pipeline.h>

#define T    512
#define K    4
#define G    20000
#define EPG  3
#define B    512

#define BT     32                  // batches per tile (= lanes)
#define NBT    (B / BT)            // 16
#define BLKG   1024                // 32 warps = 4 groups of 8
#define GPB    256                 // g per super-chunk (64 per group)
#define GPG    64                  // g per group-chunk
#define NGRP   4                   // pipeline groups per block
#define GTHR   256                 // threads per group
#define CPS    9                   // chunks per split
#define NCHUNK 81                  // 81*256 = 20736; 9 splits x 9 chunks
#define GPAD   (NCHUNK * GPB)      // 20736
#define NSPLIT 9                   // grid 16*9 = 144 ~= 1 wave
#define BLKP   512                 // prep threads

// h2 fp16, layout [bt][t][b_in] as uint2 (k0k1, k2k3): 2 MB, L2-resident.
__device__ uint2  g_h2u[NBT * T * BT];
// per-g 16B record: {e0*16, e1*16, e2*16 (int bits, uint4-index scale), b3}
__device__ float4 g_q0[GPAD];

// SMEM (bytes): h2 128K | rec 4 groups x 2 bufs x 4K | out 4 x 2 x 8K = 224K
#define S_H2   0
#define S_REC  131072                    // + gid*8192 + buf*4096
#define S_OUT  (131072 + 32768)          // + gid*16384 + buf*8192
#define SMEM_TOTAL (131072 + 32768 + 65536)

__device__ __forceinline__ float leaky(float x) {
    return x > 0.0f ? x : 0.01f * x;
}

// Packed f32x2 FMA (Blackwell FFMA2) — bit-identical to two scalar fp32 FMAs.
__device__ __forceinline__ float2 ffma2(float2 a, float2 b, float2 c) {
    float2 d;
    asm("{\n\t"
        ".reg .b64 ra, rb, rc, rd;\n\t"
        "mov.b64 ra, {%2, %3};\n\t"
        "mov.b64 rb, {%4, %5};\n\t"
        "mov.b64 rc, {%6, %7};\n\t"
        "fma.rn.f32x2 rd, ra, rb, rc;\n\t"
        "mov.b64 {%0, %1}, rd;\n\t"
        "}"
        : "=f"(d.x), "=f"(d.y)
        : "f"(a.x), "f"(a.y), "f"(b.x), "f"(b.y), "f"(c.x), "f"(c.y));
    return d;
}

// ---------------------------------------------------------------------------
// Prep: blocks [0,512) compute h2; blocks [512, 512+41) pack q0 records.
// ---------------------------------------------------------------------------
#define H2_BLOCKS   512
#define PACK_BLOCKS ((GPAD + BLKP - 1) / BLKP)   // 41

__global__ void prep_kernel(const float*  __restrict__ features,
                            const float4* __restrict__ w1,
                            const float4* __restrict__ b1,
                            const float4* __restrict__ w2,
                            const float4* __restrict__ b2,
                            const int*    __restrict__ edge,
                            const float*  __restrict__ b3) {
    const int tid = threadIdx.x;
    if (blockIdx.x < H2_BLOCKS) {
        const int b_in = tid & 31;
        const int ty   = tid >> 5;
        const int bt   = blockIdx.x & (NBT - 1);
        const int t    = (blockIdx.x >> 4) * 16 + ty;
        const int b    = bt * BT + b_in;

        const float  f   = features[b * T + t];
        const float4 w1v = w1[t];
        const float4 b1v = b1[t];
        const float4 b2v = b2[t];

        const float h0 = leaky(fmaf(f, w1v.x, b1v.x));
        const float h1 = leaky(fmaf(f, w1v.y, b1v.y));
        const float h2 = leaky(fmaf(f, w1v.z, b1v.z));
        const float h3 = leaky(fmaf(f, w1v.w, b1v.w));

        const float4 w20 = w2[t * 4 + 0];
        const float4 w21 = w2[t * 4 + 1];
        const float4 w22 = w2[t * 4 + 2];
        const float4 w23 = w2[t * 4 + 3];

        float4 o;
        o.x = leaky(fmaf(h3, w23.x, fmaf(h2, w22.x, fmaf(h1, w21.x, fmaf(h0, w20.x, b2v.x)))));
        o.y = leaky(fmaf(h3, w23.y, fmaf(h2, w22.y, fmaf(h1, w21.y, fmaf(h0, w20.y, b2v.y)))));
        o.z = leaky(fmaf(h3, w23.z, fmaf(h2, w22.z, fmaf(h1, w21.z, fmaf(h0, w20.z, b2v.z)))));
        o.w = leaky(fmaf(h3, w23.w, fmaf(h2, w22.w, fmaf(h1, w21.w, fmaf(h0, w20.w, b2v.w)))));

        const __half2 p0 = __floats2half2_rn(o.x, o.y);
        const __half2 p1 = __floats2half2_rn(o.z, o.w);
        uint2 p;
        p.x = *reinterpret_cast<const unsigned int*>(&p0);
        p.y = *reinterpret_cast<const unsigned int*>(&p1);
        g_h2u[((size_t)bt * T + t) * BT + b_in] = p;
    } else {
        const int g = (blockIdx.x - H2_BLOCKS) * BLKP + tid;
        if (g >= GPAD) return;
        float4 q = make_float4(0.f, 0.f, 0.f, 0.f);
        if (g < G) {
            // scale = 16: index into uint4-view of the h2 tile (t*16 + hb)
            q = make_float4(__int_as_float(edge[3 * g + 0] * 16),
                            __int_as_float(edge[3 * g + 1] * 16),
                            __int_as_float(edge[3 * g + 2] * 16),
                            b3[g]);
        }
        g_q0[g] = q;
    }
}

// Stage one GROUP chunk (64 g): w3 (192 float4) + q0 (64) with 256 threads.
__device__ __forceinline__ void stage_group(float4* rec, const float* w3,
                                            int go, int tg) {
    const int nvg = min(GPG, max(0, G - go));
    if (tg < GPG * 3) {                       // 0..191: w3 quarters
        if (tg < nvg * 3) {
            const float4* wsrc =
                reinterpret_cast<const float4*>(w3 + (size_t)go * 12);
            const int g = tg / 3, part = tg - g * 3;
            __pipeline_memcpy_async(&rec[g * 4 + 1 + part], &wsrc[tg], 16);
        }
    } else {                                  // 192..255: q0 records
        const int g = tg - GPG * 3;
        if (g < nvg)
            __pipeline_memcpy_async(&rec[g * 4], &g_q0[(size_t)go + g], 16);
    }
}

// ---------------------------------------------------------------------------
// Gather: persistent shared h2 tile; FOUR independent 8-warp pipeline groups
// (own rec/out double-buffers, own named barrier) — minimal barrier skew.
// ---------------------------------------------------------------------------
__global__ void __launch_bounds__(BLKG, 1)
gather_kernel(const float* __restrict__ w3, float* __restrict__ out) {
    extern __shared__ char sm[];
    const uint4* s_h2q = reinterpret_cast<const uint4*>(sm + S_H2);  // [T*16]

    const int tid  = threadIdx.x;
    const int bt   = blockIdx.y;
    const int w    = tid >> 5;
    const int lane = tid & 31;
    const int gid  = w >> 3;        // pipeline group 0..3
    const int wg   = w & 7;         // warp within group
    const int tg   = tid & (GTHR - 1);   // thread within group
    const int half = lane >> 4;     // which g of the pair
    const int hb   = lane & 15;     // batch-pair index: covers b = 2hb, 2hb+1

    float4* g_rec = reinterpret_cast<float4*>(sm + S_REC + gid * 8192);
    float*  g_out = reinterpret_cast<float*>(sm + S_OUT + gid * 16384);

    int c = blockIdx.x;   // first super-chunk for this split

    // PDL: w3 is a kernel input (independent of prep) — stage the group's
    // first w3 chunk while prep drains.
    {
        const int go = c * GPB + gid * GPG;
        const int nvg = min(GPG, max(0, G - go));
        if (tg < nvg * 3) {
            const float4* wsrc =
                reinterpret_cast<const float4*>(w3 + (size_t)go * 12);
            const int g = tg / 3, part = tg - g * 3;
            __pipeline_memcpy_async(&g_rec[g * 4 + 1 + part], &wsrc[tg], 16);
        }
    }
    __pipeline_commit();

    cudaGridDependencySynchronize();   // prep grid done (h2 + q0 ready)

    // Stage persistent h2 tile (all 1024 threads) + first chunk's q0.
    {
        const uint4* src = reinterpret_cast<const uint4*>(g_h2u + (size_t)bt * T * BT);
        uint4*       dst = reinterpret_cast<uint4*>(sm + S_H2);
        #pragma unroll
        for (int i = tid; i < T * BT / 2; i += BLKG)
            __pipeline_memcpy_async(&dst[i], &src[i], 16);
    }
    {
        const int go = c * GPB + gid * GPG;
        const int nvg = min(GPG, max(0, G - go));
        if (tg >= GPG * 3) {
            const int g = tg - GPG * 3;
            if (g < nvg)
                __pipeline_memcpy_async(&g_rec[g * 4], &g_q0[(size_t)go + g], 16);
        }
    }
    __pipeline_commit();
    __pipeline_wait_prior(0);
    __syncthreads();   // h2 tile published to the whole block

    const int barid = 1 + gid;

    #pragma unroll 1
    for (int iter = 0; iter < CPS; iter++) {
        const int  buf      = iter & 1;
        const bool has_next = (iter + 1 < CPS);

        // Prefetch group's next chunk into the other buffer.
        if (has_next) {
            stage_group(g_rec + (buf ^ 1) * (GPG * 4), w3,
                        (c + NSPLIT) * GPB + gid * GPG, tg);
            __pipeline_commit();
        }

        // Compute: warp wg owns 8 g as 4 half-warp pairs, single pass:
        // each lane serves batches 2hb and 2hb+1 via uint4 h2 loads.
        {
            const float4* rec = g_rec + buf * (GPG * 4);
            float*        ob  = g_out + buf * (GPG * 32);
            const int gl0 = wg * 8;

            #pragma unroll
            for (int pp = 0; pp < 4; pp++) {
                const int gsel = gl0 + 2 * pp + half;
                const int xs   = gsel & 31;      // xor swizzle column key

                const float4 q0 = rec[gsel * 4 + 0];
                const float4 q1 = rec[gsel * 4 + 1];
                const float4 q2 = rec[gsel * 4 + 2];
                const float4 q3 = rec[gsel * 4 + 3];

                const uint4 h0 = s_h2q[__float_as_int(q0.x) + hb];
                const uint4 h1 = s_h2q[__float_as_int(q0.y) + hb];
                const uint4 h2 = s_h2q[__float_as_int(q0.z) + hb];

                float2 a00 = make_float2(q0.w, 0.f), a01 = make_float2(0.f, 0.f);
                float2 a10 = make_float2(q0.w, 0.f), a11 = make_float2(0.f, 0.f);

                a00 = ffma2(__half22float2(*reinterpret_cast<const __half2*>(&h0.x)),
                            make_float2(q1.x, q1.y), a00);
                a01 = ffma2(__half22float2(*reinterpret_cast<const __half2*>(&h0.y)),
                            make_float2(q1.z, q1.w), a01);
                a10 = ffma2(__half22float2(*reinterpret_cast<const __half2*>(&h0.z)),
                            make_float2(q1.x, q1.y), a10);
                a11 = ffma2(__half22float2(*reinterpret_cast<const __half2*>(&h0.w)),
                            make_float2(q1.z, q1.w), a11);

                a00 = ffma2(__half22float2(*reinterpret_cast<const __half2*>(&h1.x)),
                            make_float2(q2.x, q2.y), a00);
                a01 = ffma2(__half22float2(*reinterpret_cast<const __half2*>(&h1.y)),
                            make_float2(q2.z, q2.w), a01);
                a10 = ffma2(__half22float2(*reinterpret_cast<const __half2*>(&h1.z)),
                            make_float2(q2.x, q2.y), a10);
                a11 = ffma2(__half22float2(*reinterpret_cast<const __half2*>(&h1.w)),
                            make_float2(q2.z, q2.w), a11);

                a00 = ffma2(__half22float2(*reinterpret_cast<const __half2*>(&h2.x)),
                            make_float2(q3.x, q3.y), a00);
                a01 = ffma2(__half22float2(*reinterpret_cast<const __half2*>(&h2.y)),
                            make_float2(q3.z, q3.w), a01);
                a10 = ffma2(__half22float2(*reinterpret_cast<const __half2*>(&h2.z)),
                            make_float2(q3.x, q3.y), a10);
                a11 = ffma2(__half22float2(*reinterpret_cast<const __half2*>(&h2.w)),
                            make_float2(q3.z, q3.w), a11);

                const float r0 = (a00.x + a01.x) + (a00.y + a01.y);
                const float r1 = (a10.x + a11.x) + (a10.y + a11.y);

                ob[gsel * 32 + ((2 * hb)     ^ xs)] = r0;
                ob[gsel * 32 + ((2 * hb + 1) ^ xs)] = r1;
            }
        }

        // Staging resident to this thread, then one GROUP barrier publishes
        // both s_out[buf] and the next rec buffer (256 threads only).
        if (has_next) __pipeline_wait_prior(0);
        asm volatile("bar.sync %0, %1;" :: "r"(barid), "r"(GTHR) : "memory");

        // Coalesced write-out: warp wg covers batch rows wg+{0,8,16,24}.
        {
            const float* ob = g_out + buf * (GPG * 32);
            const int gbase = c * GPB + gid * GPG;
            #pragma unroll
            for (int bh = 0; bh < 4; bh++) {
                const int b_local = wg + bh * 8;
                float* orow = out + (size_t)(bt * BT + b_local) * G + gbase;
                #pragma unroll
                for (int it2 = 0; it2 < 2; it2++) {
                    const int gl = it2 * 32 + lane;
                    if (gbase + gl < G)
                        orow[gl] = ob[gl * 32 + (b_local ^ (gl & 31))];
                }
            }
        }

        c += NSPLIT;
    }
}

extern "C" void kernel_launch(void* const* d_in, const int* in_sizes, int n_in,
                              void* d_out, int out_size) {
    const float* features = (const float*)d_in[0];   // [B, T]
    const float* w1       = (const float*)d_in[1];   // [T, K]
    const float* b1       = (const float*)d_in[2];   // [T, K]
    const float* w2       = (const float*)d_in[3];   // [T, K, K]
    const float* b2       = (const float*)d_in[4];   // [T, K]
    const float* w3       = (const float*)d_in[5];   // [G, EPG, K]
    const float* b3       = (const float*)d_in[6];   // [G]
    const int*   edge     = (const int*)  d_in[7];   // [G, EPG]
    float*       out      = (float*)d_out;           // [B, G]

    prep_kernel<<<H2_BLOCKS + PACK_BLOCKS, BLKP>>>(
        features, (const float4*)w1, (const float4*)b1,
        (const float4*)w2, (const float4*)b2, edge, b3);

    cudaFuncSetAttribute(gather_kernel,
                         cudaFuncAttributeMaxDynamicSharedMemorySize, SMEM_TOTAL);

    // PDL launch: gather may start while prep drains; it syncs on the grid
    // dependency before touching prep's outputs.
    cudaLaunchConfig_t cfg = {};
    cfg.gridDim = dim3(NSPLIT, NBT);
    cfg.blockDim = dim3(BLKG);
    cfg.dynamicSmemBytes = SMEM_TOTAL;
    cudaLaunchAttribute attrs[1];
    attrs[0].id = cudaLaunchAttributeProgrammaticStreamSerialization;
    attrs[0].val.programmaticStreamSerializationAllowed = 1;
    cfg.attrs = attrs;
    cfg.numAttrs = 1;
    cudaLaunchKernelEx(&cfg, gather_kernel, w3, out);
}

// round 16
// speedup vs baseline: 1.2171x; 1.0066x over previous
#include <cuda_runtime.h>
#include <cuda_fp16.h>
#include <cuda_pipeline.h>

#define T    512
#define K    4
#define G    20000
#define EPG  3
#define B    512

#define BT     32                  // batches per tile (= lanes)
#define NBT    (B / BT)            // 16
#define BLKG   1024                // 32 warps = 4 groups of 8
#define GPB    256                 // g per super-chunk (64 per group)
#define GPG    64                  // g per group-chunk
#define GTHR   256                 // threads per group
#define CPS    9                   // chunks per split
#define NSPLIT 9                   // grid 16*9 = 144 = 1 wave (1 block/SM)
#define TSLICE 57                  // t per split for h2 compute (9*57 >= 512)

// h2 fp16, layout [bt][t][b_in] as uint2 (k0k1, k2k3): 2 MB, L2-resident.
__device__ uint2 g_h2u[NBT * T * BT];
// per-bt arrival/departure counters for in-kernel h2 sync (zero-init; kernel
// resets them at exit so graph replays start clean).
__device__ int g_arrive[NBT];
__device__ int g_depart[NBT];

// SMEM (bytes): h2 128K | rec 4 groups x 2 bufs x 4K | out 4 x 2 x 8K = 224K
#define S_H2   0
#define S_REC  131072                    // + gid*8192 + buf*4096
#define S_OUT  (131072 + 32768)          // + gid*16384 + buf*8192
#define SMEM_TOTAL (131072 + 32768 + 65536)

__device__ __forceinline__ float leaky(float x) {
    return x > 0.0f ? x : 0.01f * x;
}

// Packed f32x2 FMA (Blackwell FFMA2) — bit-identical to two scalar fp32 FMAs.
__device__ __forceinline__ float2 ffma2(float2 a, float2 b, float2 c) {
    float2 d;
    asm("{\n\t"
        ".reg .b64 ra, rb, rc, rd;\n\t"
        "mov.b64 ra, {%2, %3};\n\t"
        "mov.b64 rb, {%4, %5};\n\t"
        "mov.b64 rc, {%6, %7};\n\t"
        "fma.rn.f32x2 rd, ra, rb, rc;\n\t"
        "mov.b64 {%0, %1}, rd;\n\t"
        "}"
        : "=f"(d.x), "=f"(d.y)
        : "f"(a.x), "f"(a.y), "f"(b.x), "f"(b.y), "f"(c.x), "f"(c.y));
    return d;
}

// Stage one GROUP chunk (64 g) from RAW inputs with 256 threads:
//   tg in [0,64):    pack q0 = {e0*16, e1*16, e2*16, b3} via LDG -> STS
//   tg in [64,256):  w3 quarters via cp.async (192 float4)
// Publication: STS + cp.async both ordered by the subsequent group barrier
// (cp.async additionally by __pipeline_wait_prior before that barrier).
__device__ __forceinline__ void stage_rec(float4* rec,
                                          const int*   __restrict__ edge,
                                          const float* __restrict__ b3,
                                          const float* __restrict__ w3,
                                          int go, int tg) {
    if (tg < GPG) {
        const int g = go + tg;
        float4 q;
        if (g < G) {
            q = make_float4(__int_as_float(edge[3 * g + 0] * 16),
                            __int_as_float(edge[3 * g + 1] * 16),
                            __int_as_float(edge[3 * g + 2] * 16),
                            b3[g]);
        } else {
            q = make_float4(__int_as_float(0), __int_as_float(0),
                            __int_as_float(0), 0.f);
        }
        rec[tg * 4] = q;
    } else {
        const int i = tg - GPG;                     // 0..191
        const int nvg = min(GPG, max(0, G - go));
        if (i < nvg * 3) {
            const float4* wsrc =
                reinterpret_cast<const float4*>(w3 + (size_t)go * 12);
            const int g = i / 3, part = i - g * 3;
            __pipeline_memcpy_async(&rec[g * 4 + 1 + part], &wsrc[i], 16);
        }
    }
}

// ---------------------------------------------------------------------------
// Single fused kernel. Phase A: each of the 9 blocks per bt computes a 57-t
// slice of that bt's h2 into global, then per-bt flag sync (all 144 blocks
// are co-resident: grid = 1 wave). Phase B: R15's 4-group gather pipeline.
// ---------------------------------------------------------------------------
__global__ void __launch_bounds__(BLKG, 1)
fused_kernel(const float*  __restrict__ features,
             const float4* __restrict__ w1,
             const float4* __restrict__ b1,
             const float4* __restrict__ w2,
             const float4* __restrict__ b2,
             const float*  __restrict__ w3,
             const float*  __restrict__ b3,
             const int*    __restrict__ edge,
             float*        __restrict__ out) {
    extern __shared__ char sm[];
    const uint4* s_h2q = reinterpret_cast<const uint4*>(sm + S_H2);  // [T*16]

    const int tid   = threadIdx.x;
    const int split = blockIdx.x;   // 0..8
    const int bt    = blockIdx.y;   // 0..15
    const int w     = tid >> 5;
    const int lane  = tid & 31;
    const int gid   = w >> 3;             // pipeline group 0..3
    const int wg    = w & 7;              // warp within group
    const int tg    = tid & (GTHR - 1);   // thread within group
    const int half  = lane >> 4;
    const int hb    = lane & 15;

    float4* g_rec = reinterpret_cast<float4*>(sm + S_REC + gid * 8192);
    float*  g_out = reinterpret_cast<float*>(sm + S_OUT + gid * 16384);

    // ---- Phase A1: compute this block's h2 slice (t in [split*57, +57)) ----
    {
        const int t0   = split * TSLICE;
        const int tcnt = min(TSLICE, T - t0);        // 57 (56 for split 8)
        const int n    = tcnt * BT;
        for (int i = tid; i < n; i += BLKG) {
            const int t    = t0 + (i >> 5);
            const int b_in = i & 31;
            const int b    = bt * BT + b_in;

            const float  f   = features[b * T + t];
            const float4 w1v = w1[t];
            const float4 b1v = b1[t];
            const float4 b2v = b2[t];

            const float h0 = leaky(fmaf(f, w1v.x, b1v.x));
            const float h1 = leaky(fmaf(f, w1v.y, b1v.y));
            const float h2 = leaky(fmaf(f, w1v.z, b1v.z));
            const float h3 = leaky(fmaf(f, w1v.w, b1v.w));

            const float4 w20 = w2[t * 4 + 0];
            const float4 w21 = w2[t * 4 + 1];
            const float4 w22 = w2[t * 4 + 2];
            const float4 w23 = w2[t * 4 + 3];

            float4 o;
            o.x = leaky(fmaf(h3, w23.x, fmaf(h2, w22.x, fmaf(h1, w21.x, fmaf(h0, w20.x, b2v.x)))));
            o.y = leaky(fmaf(h3, w23.y, fmaf(h2, w22.y, fmaf(h1, w21.y, fmaf(h0, w20.y, b2v.y)))));
            o.z = leaky(fmaf(h3, w23.z, fmaf(h2, w22.z, fmaf(h1, w21.z, fmaf(h0, w20.z, b2v.z)))));
            o.w = leaky(fmaf(h3, w23.w, fmaf(h2, w22.w, fmaf(h1, w21.w, fmaf(h0, w20.w, b2v.w)))));

            const __half2 p0 = __floats2half2_rn(o.x, o.y);
            const __half2 p1 = __floats2half2_rn(o.z, o.w);
            uint2 p;
            p.x = *reinterpret_cast<const unsigned int*>(&p0);
            p.y = *reinterpret_cast<const unsigned int*>(&p1);
            g_h2u[((size_t)bt * T + t) * BT + b_in] = p;
        }
    }
    __threadfence();          // publish this thread's h2 writes (GPU scope)
    __syncthreads();          // all fences in this block done
    if (tid == 0) atomicAdd(&g_arrive[bt], 1);

    // ---- Phase A2: stage chunk-0 records (prep-independent raw inputs) ----
    int c = split;   // first super-chunk for this split
    stage_rec(g_rec, edge, b3, w3, c * GPB + gid * GPG, tg);
    __pipeline_commit();

    // ---- Phase A3: wait for all 9 sibling blocks of this bt column ----
    if (tid == 0) {
        while (*((volatile int*)&g_arrive[bt]) < NSPLIT) { }
        __threadfence();      // acquire: order subsequent h2 reads
    }
    __syncthreads();

    // ---- Phase A4: stage the persistent 128 KB h2 tile ----
    {
        const uint4* src = reinterpret_cast<const uint4*>(g_h2u + (size_t)bt * T * BT);
        uint4*       dst = reinterpret_cast<uint4*>(sm + S_H2);
        #pragma unroll
        for (int i = tid; i < T * BT / 2; i += BLKG)
            __pipeline_memcpy_async(&dst[i], &src[i], 16);
    }
    __pipeline_commit();
    __pipeline_wait_prior(0);
    __syncthreads();          // h2 tile + chunk-0 rec published

    const int barid = 1 + gid;

    // ---- Phase B: 4-group gather pipeline (identical body to R15) ----
    #pragma unroll 1
    for (int iter = 0; iter < CPS; iter++) {
        const int  buf      = iter & 1;
        const bool has_next = (iter + 1 < CPS);

        if (has_next) {
            stage_rec(g_rec + (buf ^ 1) * (GPG * 4), edge, b3, w3,
                      (c + NSPLIT) * GPB + gid * GPG, tg);
            __pipeline_commit();
        }

        {
            const float4* rec = g_rec + buf * (GPG * 4);
            float*        ob  = g_out + buf * (GPG * 32);
            const int gl0 = wg * 8;

            #pragma unroll
            for (int pp = 0; pp < 4; pp++) {
                const int gsel = gl0 + 2 * pp + half;
                const int xs   = gsel & 31;

                const float4 q0 = rec[gsel * 4 + 0];
                const float4 q1 = rec[gsel * 4 + 1];
                const float4 q2 = rec[gsel * 4 + 2];
                const float4 q3 = rec[gsel * 4 + 3];

                const uint4 h0 = s_h2q[__float_as_int(q0.x) + hb];
                const uint4 h1 = s_h2q[__float_as_int(q0.y) + hb];
                const uint4 h2 = s_h2q[__float_as_int(q0.z) + hb];

                float2 a00 = make_float2(q0.w, 0.f), a01 = make_float2(0.f, 0.f);
                float2 a10 = make_float2(q0.w, 0.f), a11 = make_float2(0.f, 0.f);

                a00 = ffma2(__half22float2(*reinterpret_cast<const __half2*>(&h0.x)),
                            make_float2(q1.x, q1.y), a00);
                a01 = ffma2(__half22float2(*reinterpret_cast<const __half2*>(&h0.y)),
                            make_float2(q1.z, q1.w), a01);
                a10 = ffma2(__half22float2(*reinterpret_cast<const __half2*>(&h0.z)),
                            make_float2(q1.x, q1.y), a10);
                a11 = ffma2(__half22float2(*reinterpret_cast<const __half2*>(&h0.w)),
                            make_float2(q1.z, q1.w), a11);

                a00 = ffma2(__half22float2(*reinterpret_cast<const __half2*>(&h1.x)),
                            make_float2(q2.x, q2.y), a00);
                a01 = ffma2(__half22float2(*reinterpret_cast<const __half2*>(&h1.y)),
                            make_float2(q2.z, q2.w), a01);
                a10 = ffma2(__half22float2(*reinterpret_cast<const __half2*>(&h1.z)),
                            make_float2(q2.x, q2.y), a10);
                a11 = ffma2(__half22float2(*reinterpret_cast<const __half2*>(&h1.w)),
                            make_float2(q2.z, q2.w), a11);

                a00 = ffma2(__half22float2(*reinterpret_cast<const __half2*>(&h2.x)),
                            make_float2(q3.x, q3.y), a00);
                a01 = ffma2(__half22float2(*reinterpret_cast<const __half2*>(&h2.y)),
                            make_float2(q3.z, q3.w), a01);
                a10 = ffma2(__half22float2(*reinterpret_cast<const __half2*>(&h2.z)),
                            make_float2(q3.x, q3.y), a10);
                a11 = ffma2(__half22float2(*reinterpret_cast<const __half2*>(&h2.w)),
                            make_float2(q3.z, q3.w), a11);

                const float r0 = (a00.x + a01.x) + (a00.y + a01.y);
                const float r1 = (a10.x + a11.x) + (a10.y + a11.y);

                ob[gsel * 32 + ((2 * hb)     ^ xs)] = r0;
                ob[gsel * 32 + ((2 * hb + 1) ^ xs)] = r1;
            }
        }

        if (has_next) __pipeline_wait_prior(0);
        asm volatile("bar.sync %0, %1;" :: "r"(barid), "r"(GTHR) : "memory");

        // Coalesced write-out: warp wg covers batch rows wg+{0,8,16,24}.
        {
            const float* ob = g_out + buf * (GPG * 32);
            const int gbase = c * GPB + gid * GPG;
            #pragma unroll
            for (int bh = 0; bh < 4; bh++) {
                const int b_local = wg + bh * 8;
                float* orow = out + (size_t)(bt * BT + b_local) * G + gbase;
                #pragma unroll
                for (int it2 = 0; it2 < 2; it2++) {
                    const int gl = it2 * 32 + lane;
                    if (gbase + gl < G)
                        orow[gl] = ob[gl * 32 + (b_local ^ (gl & 31))];
                }
            }
        }

        c += NSPLIT;
    }

    // ---- Epilogue: counter reset so graph replays start from zero ----
    if (tid == 0) {
        atomicAdd(&g_depart[bt], 1);
        if (split == 0) {
            while (*((volatile int*)&g_depart[bt]) < NSPLIT) { }
            atomicExch(&g_arrive[bt], 0);
            atomicExch(&g_depart[bt], 0);
        }
    }
}

extern "C" void kernel_launch(void* const* d_in, const int* in_sizes, int n_in,
                              void* d_out, int out_size) {
    const float* features = (const float*)d_in[0];   // [B, T]
    const float* w1       = (const float*)d_in[1];   // [T, K]
    const float* b1       = (const float*)d_in[2];   // [T, K]
    const float* w2       = (const float*)d_in[3];   // [T, K, K]
    const float* b2       = (const float*)d_in[4];   // [T, K]
    const float* w3       = (const float*)d_in[5];   // [G, EPG, K]
    const float* b3       = (const float*)d_in[6];   // [G]
    const int*   edge     = (const int*)  d_in[7];   // [G, EPG]
    float*       out      = (float*)d_out;           // [B, G]

    cudaFuncSetAttribute(fused_kernel,
                         cudaFuncAttributeMaxDynamicSharedMemorySize, SMEM_TOTAL);
    dim3 grid(NSPLIT, NBT);
    fused_kernel<<<grid, BLKG, SMEM_TOTAL>>>(
        features, (const float4*)w1, (const float4*)b1,
        (const float4*)w2, (const float4*)b2,
        w3, b3, edge, out);
}